// round 15
// baseline (speedup 1.0000x reference)
#include <cuda_runtime.h>
#include <cuda_fp16.h>
#include <math.h>

#define NU 100000
#define NI 50000
#define DD 64
#define NE 2000000
#define NTOT (NU + NI)
#define SPART 128

// ----------------------------- scratch --------------------------------------
__device__ __half2 g_img_h[NI * 32];
__device__ __half2 g_txt_h[NI * 32];
__device__ __half2 g_in_h[NI * 32];
__device__ __half2 g_imgU_h[NU * 32];
__device__ __half2 g_txtU_h[NU * 32];
__device__ __half2 g_ue1_h[NU * 32];
__device__ __half2 g_ie1_h[NI * 32];
__device__ __half2 g_ue2_h[NU * 32];

__device__ float g_u_acc[NU * DD];
__device__ float g_i_acc[NI * DD];

__device__ int   g_cnt_u[NU];
__device__ int   g_offs_u[NU + 1];
__device__ int   g_cnt_i[NI];
__device__ int   g_offs_i[NI + 1];
__device__ unsigned short g_rank_u[NE];
__device__ unsigned short g_rank_i[NE];

__device__ int2  g_edge_u[NE];
__device__ int2  g_edge_i[NE];

__device__ float g_part[SPART * DD];
__device__ float g_part1[SPART];
__device__ float g_colmean[DD];
__device__ float g_invrnm;

// ----------------------------- CSR build (per side, unroll-4) ----------------
__global__ void k_hist_u(const int* __restrict__ eu) {
    int i = blockIdx.x * blockDim.x + threadIdx.x;
    int st = gridDim.x * blockDim.x;
    int e = i;
    for (; e + 3 * st < NE; e += 4 * st) {
        int u0 = eu[e], u1 = eu[e + st], u2 = eu[e + 2 * st], u3 = eu[e + 3 * st];
        g_rank_u[e]          = (unsigned short)atomicAdd(&g_cnt_u[u0], 1);
        g_rank_u[e + st]     = (unsigned short)atomicAdd(&g_cnt_u[u1], 1);
        g_rank_u[e + 2 * st] = (unsigned short)atomicAdd(&g_cnt_u[u2], 1);
        g_rank_u[e + 3 * st] = (unsigned short)atomicAdd(&g_cnt_u[u3], 1);
    }
    for (; e < NE; e += st)
        g_rank_u[e] = (unsigned short)atomicAdd(&g_cnt_u[eu[e]], 1);
}

__global__ void k_hist_i(const int* __restrict__ ei) {
    int i = blockIdx.x * blockDim.x + threadIdx.x;
    int st = gridDim.x * blockDim.x;
    int e = i;
    for (; e + 3 * st < NE; e += 4 * st) {
        int u0 = ei[e], u1 = ei[e + st], u2 = ei[e + 2 * st], u3 = ei[e + 3 * st];
        g_rank_i[e]          = (unsigned short)atomicAdd(&g_cnt_i[u0], 1);
        g_rank_i[e + st]     = (unsigned short)atomicAdd(&g_cnt_i[u1], 1);
        g_rank_i[e + 2 * st] = (unsigned short)atomicAdd(&g_cnt_i[u2], 1);
        g_rank_i[e + 3 * st] = (unsigned short)atomicAdd(&g_cnt_i[u3], 1);
    }
    for (; e < NE; e += st)
        g_rank_i[e] = (unsigned short)atomicAdd(&g_cnt_i[ei[e]], 1);
}

template <int SIDE>
__global__ void k_scan() {
    const int* cnt = SIDE ? g_cnt_i : g_cnt_u;
    int* offs      = SIDE ? g_offs_i : g_offs_u;
    const int n    = SIDE ? NI : NU;

    __shared__ int warpsum[32];
    __shared__ int s_carry;
    int t = threadIdx.x, lane = t & 31, w = t >> 5;
    if (t == 0) { s_carry = 0; offs[0] = 0; }
    __syncthreads();

    for (int base = 0; base < n; base += 1024) {
        int i = base + t;
        int v = (i < n) ? cnt[i] : 0;
        int x = v;
#pragma unroll
        for (int d = 1; d < 32; d <<= 1) {
            int y = __shfl_up_sync(0xffffffffu, x, d);
            if (lane >= d) x += y;
        }
        if (lane == 31) warpsum[w] = x;
        __syncthreads();
        if (w == 0) {
            int ws = warpsum[lane];
#pragma unroll
            for (int d = 1; d < 32; d <<= 1) {
                int y = __shfl_up_sync(0xffffffffu, ws, d);
                if (lane >= d) ws += y;
            }
            warpsum[lane] = ws;
        }
        __syncthreads();
        int inc = x + (w ? warpsum[w - 1] : 0) + s_carry;
        if (i < n) offs[i + 1] = inc;
        __syncthreads();
        if (t == 1023) s_carry = inc;
        __syncthreads();
    }
}

__global__ void k_scatter_u(const int* __restrict__ eu, const int* __restrict__ ei,
                            const float* __restrict__ vui) {
    int i = blockIdx.x * blockDim.x + threadIdx.x;
    int st = gridDim.x * blockDim.x;
    int e = i;
    for (; e + 3 * st < NE; e += 4 * st) {
        int u0 = eu[e], u1 = eu[e + st], u2 = eu[e + 2 * st], u3 = eu[e + 3 * st];
        int s0 = ei[e], s1 = ei[e + st], s2 = ei[e + 2 * st], s3 = ei[e + 3 * st];
        float v0 = vui[e], v1 = vui[e + st], v2 = vui[e + 2 * st], v3 = vui[e + 3 * st];
        int r0 = g_rank_u[e], r1 = g_rank_u[e + st];
        int r2 = g_rank_u[e + 2 * st], r3 = g_rank_u[e + 3 * st];
        int o0 = g_offs_u[u0], o1 = g_offs_u[u1], o2 = g_offs_u[u2], o3 = g_offs_u[u3];
        g_edge_u[o0 + r0] = make_int2(s0, __float_as_int(v0));
        g_edge_u[o1 + r1] = make_int2(s1, __float_as_int(v1));
        g_edge_u[o2 + r2] = make_int2(s2, __float_as_int(v2));
        g_edge_u[o3 + r3] = make_int2(s3, __float_as_int(v3));
    }
    for (; e < NE; e += st) {
        int u = eu[e];
        int p = g_offs_u[u] + (int)g_rank_u[e];
        g_edge_u[p] = make_int2(ei[e], __float_as_int(vui[e]));
    }
}

__global__ void k_scatter_i(const int* __restrict__ eu, const int* __restrict__ ei,
                            const float* __restrict__ viu) {
    int i = blockIdx.x * blockDim.x + threadIdx.x;
    int st = gridDim.x * blockDim.x;
    int e = i;
    for (; e + 3 * st < NE; e += 4 * st) {
        int u0 = ei[e], u1 = ei[e + st], u2 = ei[e + 2 * st], u3 = ei[e + 3 * st];
        int s0 = eu[e], s1 = eu[e + st], s2 = eu[e + 2 * st], s3 = eu[e + 3 * st];
        float v0 = viu[e], v1 = viu[e + st], v2 = viu[e + 2 * st], v3 = viu[e + 3 * st];
        int r0 = g_rank_i[e], r1 = g_rank_i[e + st];
        int r2 = g_rank_i[e + 2 * st], r3 = g_rank_i[e + 3 * st];
        int o0 = g_offs_i[u0], o1 = g_offs_i[u1], o2 = g_offs_i[u2], o3 = g_offs_i[u3];
        g_edge_i[o0 + r0] = make_int2(s0, __float_as_int(v0));
        g_edge_i[o1 + r1] = make_int2(s1, __float_as_int(v1));
        g_edge_i[o2 + r2] = make_int2(s2, __float_as_int(v2));
        g_edge_i[o3 + r3] = make_int2(s3, __float_as_int(v3));
    }
    for (; e < NE; e += st) {
        int it = ei[e];
        int q = g_offs_i[it] + (int)g_rank_i[e];
        g_edge_i[q] = make_int2(eu[e], __float_as_int(viu[e]));
    }
}

// ----------------------------- tensor-core linear (K-chunked smem) ----------
__device__ __forceinline__ void mma16816(float* c, unsigned a0, unsigned a1,
                                         unsigned a2, unsigned a3,
                                         unsigned b0, unsigned b1) {
    asm volatile(
        "mma.sync.aligned.m16n8k16.row.col.f32.f16.f16.f32 "
        "{%0,%1,%2,%3}, {%4,%5,%6,%7}, {%8,%9}, {%0,%1,%2,%3};"
        : "+f"(c[0]), "+f"(c[1]), "+f"(c[2]), "+f"(c[3])
        : "r"(a0), "r"(a1), "r"(a2), "r"(a3), "r"(b0), "r"(b1));
}

__device__ __forceinline__ unsigned h2u(float lo, float hi) {
    __half2 h = __floats2half2_rn(lo, hi);
    return *reinterpret_cast<unsigned*>(&h);
}

// Block = 256 rows (16 warps x 16). W^T staged in 64x128 fp16 chunks
// (17.4 KB static smem) so other streams' blocks can co-reside on the SM.
template <int K, int WHICH>
__global__ __launch_bounds__(512) void k_linear_mma(const float* __restrict__ A,
                                                    const float* __restrict__ W,
                                                    const float* __restrict__ bias,
                                                    int M) {
    constexpr int CH = 128;          // K-chunk
    constexpr int PS = CH + 8;       // padded chunk stride in halves
    __shared__ __half sWT[64 * PS];  // 17408 B
    __half* out = (__half*)(WHICH ? g_txt_h : g_img_h);

    int tid = threadIdx.x;
    int lane = tid & 31, warp = tid >> 5;
    int g = lane >> 2, q = lane & 3;
    int m_base = blockIdx.x * 256 + warp * 16;
    int row0 = m_base + g, row1 = row0 + 8;
    int r0 = min(row0, M - 1), r1 = min(row1, M - 1);
    const float* A0 = A + (size_t)r0 * K + q * 2;
    const float* A1 = A + (size_t)r1 * K + q * 2;

    float acc[8][4];
#pragma unroll
    for (int nt = 0; nt < 8; nt++)
#pragma unroll
        for (int j = 0; j < 4; j++) acc[nt][j] = 0.f;

    for (int kc0 = 0; kc0 < K; kc0 += CH) {
        __syncthreads();  // protect previous chunk's reads
#pragma unroll
        for (int i = tid; i < CH * 64; i += 512) {
            int k = i >> 6, n = i & 63;
            sWT[n * PS + k] = __float2half(W[(size_t)(kc0 + k) * 64 + n]);
        }
        __syncthreads();

#pragma unroll
        for (int kc = 0; kc < CH; kc += 64) {
            float2 fa[4][4];
#pragma unroll
            for (int c = 0; c < 4; c++) {
                int kb = kc0 + kc + c * 16;
                fa[c][0] = *(const float2*)(A0 + kb);
                fa[c][1] = *(const float2*)(A1 + kb);
                fa[c][2] = *(const float2*)(A0 + kb + 8);
                fa[c][3] = *(const float2*)(A1 + kb + 8);
            }
#pragma unroll
            for (int c = 0; c < 4; c++) {
                unsigned a0 = h2u(fa[c][0].x, fa[c][0].y);
                unsigned a1 = h2u(fa[c][1].x, fa[c][1].y);
                unsigned a2 = h2u(fa[c][2].x, fa[c][2].y);
                unsigned a3 = h2u(fa[c][3].x, fa[c][3].y);
                int kb = kc + c * 16 + q * 2;  // within-chunk smem index
#pragma unroll
                for (int nt = 0; nt < 8; nt++) {
                    int n = nt * 8 + g;
                    unsigned b0 = *(const unsigned*)&sWT[n * PS + kb];
                    unsigned b1 = *(const unsigned*)&sWT[n * PS + kb + 8];
                    mma16816(acc[nt], a0, a1, a2, a3, b0, b1);
                }
            }
        }
    }

#pragma unroll
    for (int nt = 0; nt < 8; nt++) {
        int col = nt * 8 + q * 2;
        float bx = bias[col], by = bias[col + 1];
        if (row0 < M) {
            __half2 h0 = __floats2half2_rn(acc[nt][0] + bx, acc[nt][1] + by);
            *(unsigned*)&out[(size_t)row0 * 64 + col] = *reinterpret_cast<unsigned*>(&h0);
        }
        if (row1 < M) {
            __half2 h1 = __floats2half2_rn(acc[nt][2] + bx, acc[nt][3] + by);
            *(unsigned*)&out[(size_t)row1 * 64 + col] = *reinterpret_cast<unsigned*>(&h1);
        }
    }
}

// ----------------------------- single-pass stats -----------------------------
__global__ __launch_bounds__(256) void k_stats(const float* __restrict__ ue,
                                               const float* __restrict__ ie) {
    int t = threadIdx.x, col = t & 63, rg = t >> 6;
    float s = 0.f, q = 0.f;
    for (int row = blockIdx.x * 4 + rg; row < NTOT; row += SPART * 4) {
        const float* p = (row < NU) ? ue + (size_t)row * 64 : ie + (size_t)(row - NU) * 64;
        float x = p[col];
        s += x;
        q += x * x;
    }
    __shared__ float sm[256];
    __shared__ float sq[256];
    sm[t] = s;
    sq[t] = q;
    __syncthreads();
    if (t < 64) g_part[blockIdx.x * 64 + t] = sm[t] + sm[t + 64] + sm[t + 128] + sm[t + 192];
    for (int o = 128; o >= 32; o >>= 1) {
        if (t < o) sq[t] += sq[t + o];
        __syncthreads();
    }
    if (t < 32) {
        float v = sq[t];
#pragma unroll
        for (int o = 16; o; o >>= 1) v += __shfl_xor_sync(0xffffffffu, v, o);
        if (t == 0) g_part1[blockIdx.x] = v;
    }
}

__global__ void k_stats_fin() {
    __shared__ float smean[64];
    __shared__ float red[128];
    int t = threadIdx.x;
    if (t < 64) {
        float s = 0.f;
#pragma unroll 8
        for (int b = 0; b < SPART; b++) s += g_part[b * 64 + t];
        float m = s / (float)NTOT;
        g_colmean[t] = m;
        smean[t] = m;
    }
    __syncthreads();
    float v = g_part1[t];
    if (t < 64) v -= (float)NTOT * smean[t] * smean[t];
    red[t] = v;
    __syncthreads();
    for (int o = 64; o >= 32; o >>= 1) {
        if (t < o) red[t] += red[t + o];
        __syncthreads();
    }
    if (t < 32) {
        float x = red[t];
#pragma unroll
        for (int o = 16; o; o >>= 1) x += __shfl_xor_sync(0xffffffffu, x, o);
        if (t == 0) g_invrnm = rsqrtf(x / (float)NTOT + 1e-6f);
    }
}

__global__ void k_norm_items(const float* __restrict__ ie) {
    float inv = g_invrnm;
    int st = gridDim.x * blockDim.x;
    int i0 = blockIdx.x * blockDim.x + threadIdx.x;
    const float4* i4 = (const float4*)ie;
    const float4* cm4 = (const float4*)g_colmean;
    __half* oh = (__half*)g_in_h;
    for (int idx = i0; idx < NI * 16; idx += st) {
        float4 v = i4[idx];
        float4 cm = cm4[idx & 15];
        __half2 h0 = __floats2half2_rn((v.x - cm.x) * inv, (v.y - cm.y) * inv);
        __half2 h1 = __floats2half2_rn((v.z - cm.z) * inv, (v.w - cm.w) * inv);
        uint2 s;
        s.x = *reinterpret_cast<unsigned*>(&h0);
        s.y = *reinterpret_cast<unsigned*>(&h1);
        *(uint2*)&oh[(size_t)idx * 4] = s;
    }
}

// ----------------------------- fused triple SpMM (2 rows/warp) --------------
__device__ __forceinline__ void fma_h2(float4& acc, float v, const uint2& raw) {
    float2 x0 = __half22float2(*reinterpret_cast<const __half2*>(&raw.x));
    float2 x1 = __half22float2(*reinterpret_cast<const __half2*>(&raw.y));
    acc.x += v * x0.x; acc.y += v * x0.y;
    acc.z += v * x1.x; acc.w += v * x1.y;
}

__global__ __launch_bounds__(256) void k_fused_u(const float* __restrict__ user_emb,
                                                 float* __restrict__ imgU,
                                                 float* __restrict__ txtU) {
    int warp = (blockIdx.x * 256 + threadIdx.x) >> 5;
    int lane = threadIdx.x & 31;
    int row = warp * 2 + (lane >> 4);
    if (row >= NU) return;
    int c = lane & 15;
    const uint2* __restrict__ MI = (const uint2*)g_img_h;
    const uint2* __restrict__ MT = (const uint2*)g_txt_h;
    const uint2* __restrict__ ME = (const uint2*)g_in_h;
    const int2* __restrict__ E = g_edge_u;
    int s = g_offs_u[row], e = g_offs_u[row + 1];
    float4 aI = make_float4(0.f, 0.f, 0.f, 0.f), aT = aI, aE = aI;
    for (int k = s; k < e; k += 8) {
        int2 ev[8];
#pragma unroll
        for (int u = 0; u < 8; u++) {
            int kk = k + u;
            int idx = (kk < e) ? kk : s;
            ev[u] = __ldg(&E[idx]);
            if (kk >= e) ev[u].y = 0;
        }
        uint2 ri[8], rt[8], re[8];
#pragma unroll
        for (int u = 0; u < 8; u++) {
            int b = ev[u].x * 16 + c;
            ri[u] = MI[b];
            rt[u] = MT[b];
            re[u] = ME[b];
        }
#pragma unroll
        for (int u = 0; u < 8; u++) {
            float v = __int_as_float(ev[u].y);
            fma_h2(aI, v, ri[u]);
            fma_h2(aT, v, rt[u]);
            fma_h2(aE, v, re[u]);
        }
    }
    int o = row * 16 + c;
    ((float4*)imgU)[o] = aI;
    ((float4*)txtU)[o] = aT;
    {
        __half2 h0 = __floats2half2_rn(aI.x, aI.y);
        __half2 h1 = __floats2half2_rn(aI.z, aI.w);
        uint2 st = {*reinterpret_cast<unsigned*>(&h0), *reinterpret_cast<unsigned*>(&h1)};
        ((uint2*)g_imgU_h)[o] = st;
        h0 = __floats2half2_rn(aT.x, aT.y);
        h1 = __floats2half2_rn(aT.z, aT.w);
        st.x = *reinterpret_cast<unsigned*>(&h0);
        st.y = *reinterpret_cast<unsigned*>(&h1);
        ((uint2*)g_txtU_h)[o] = st;
        h0 = __floats2half2_rn(aE.x, aE.y);
        h1 = __floats2half2_rn(aE.z, aE.w);
        st.x = *reinterpret_cast<unsigned*>(&h0);
        st.y = *reinterpret_cast<unsigned*>(&h1);
        ((uint2*)g_ue1_h)[o] = st;
    }
    float inv = g_invrnm;
    float4 ue = ((const float4*)user_emb)[o];
    float4 cm = ((const float4*)g_colmean)[c];
    float4 acc;
    acc.x = (ue.x - cm.x) * inv + aE.x;
    acc.y = (ue.y - cm.y) * inv + aE.y;
    acc.z = (ue.z - cm.z) * inv + aE.z;
    acc.w = (ue.w - cm.w) * inv + aE.w;
    ((float4*)g_u_acc)[o] = acc;
}

__global__ __launch_bounds__(256) void k_fused_i(const float* __restrict__ item_emb,
                                                 float* __restrict__ imgI,
                                                 float* __restrict__ txtI) {
    int warp = (blockIdx.x * 256 + threadIdx.x) >> 5;
    int lane = threadIdx.x & 31;
    int row = warp * 2 + (lane >> 4);
    if (row >= NI) return;
    int c = lane & 15;
    const uint2* __restrict__ MI = (const uint2*)g_imgU_h;
    const uint2* __restrict__ MT = (const uint2*)g_txtU_h;
    const uint2* __restrict__ ME = (const uint2*)g_ue1_h;
    const int2* __restrict__ E = g_edge_i;
    int s = g_offs_i[row], e = g_offs_i[row + 1];
    float4 aI = make_float4(0.f, 0.f, 0.f, 0.f), aT = aI, aE = aI;
    for (int k = s; k < e; k += 8) {
        int2 ev[8];
#pragma unroll
        for (int u = 0; u < 8; u++) {
            int kk = k + u;
            int idx = (kk < e) ? kk : s;
            ev[u] = __ldg(&E[idx]);
            if (kk >= e) ev[u].y = 0;
        }
        uint2 ri[8], rt[8], re[8];
#pragma unroll
        for (int u = 0; u < 8; u++) {
            int b = ev[u].x * 16 + c;
            ri[u] = MI[b];
            rt[u] = MT[b];
            re[u] = ME[b];
        }
#pragma unroll
        for (int u = 0; u < 8; u++) {
            float v = __int_as_float(ev[u].y);
            fma_h2(aI, v, ri[u]);
            fma_h2(aT, v, rt[u]);
            fma_h2(aE, v, re[u]);
        }
    }
    int o = row * 16 + c;
    ((float4*)imgI)[o] = aI;
    ((float4*)txtI)[o] = aT;
    {
        __half2 h0 = __floats2half2_rn(aE.x, aE.y);
        __half2 h1 = __floats2half2_rn(aE.z, aE.w);
        uint2 st = {*reinterpret_cast<unsigned*>(&h0), *reinterpret_cast<unsigned*>(&h1)};
        ((uint2*)g_ie1_h)[o] = st;
    }
    float inv = g_invrnm;
    float4 ie = ((const float4*)item_emb)[o];
    float4 cm = ((const float4*)g_colmean)[c];
    float4 acc;
    acc.x = (ie.x - cm.x) * inv + aE.x;
    acc.y = (ie.y - cm.y) * inv + aE.y;
    acc.z = (ie.z - cm.z) * inv + aE.z;
    acc.w = (ie.w - cm.w) * inv + aE.w;
    ((float4*)g_i_acc)[o] = acc;
}

// ----------------------------- layer-2 GNN + final combine -------------------
__global__ __launch_bounds__(256) void k_gnn_u2(const float* __restrict__ imgU,
                                                const float* __restrict__ txtU,
                                                float* __restrict__ u_out) {
    int warp = (blockIdx.x * 256 + threadIdx.x) >> 5;
    int lane = threadIdx.x & 31;
    int row = warp * 2 + (lane >> 4);
    if (row >= NU) return;
    int c = lane & 15;
    const uint2* __restrict__ X = (const uint2*)g_ie1_h;
    const int2* __restrict__ E = g_edge_u;
    int s = g_offs_u[row], e = g_offs_u[row + 1];
    float4 acc = make_float4(0.f, 0.f, 0.f, 0.f);
    for (int k = s; k < e; k += 8) {
        int2 ev[8];
#pragma unroll
        for (int u = 0; u < 8; u++) {
            int kk = k + u;
            int idx = (kk < e) ? kk : s;
            ev[u] = __ldg(&E[idx]);
            if (kk >= e) ev[u].y = 0;
        }
        uint2 raw[8];
#pragma unroll
        for (int u = 0; u < 8; u++) raw[u] = X[ev[u].x * 16 + c];
#pragma unroll
        for (int u = 0; u < 8; u++) fma_h2(acc, __int_as_float(ev[u].y), raw[u]);
    }
    int o = row * 16 + c;
    {
        __half2 h0 = __floats2half2_rn(acc.x, acc.y);
        __half2 h1 = __floats2half2_rn(acc.z, acc.w);
        uint2 st = {*reinterpret_cast<unsigned*>(&h0), *reinterpret_cast<unsigned*>(&h1)};
        ((uint2*)g_ue2_h)[o] = st;
    }
    float4 g = ((const float4*)g_u_acc)[o];
    float4 a = ((const float4*)imgU)[o];
    float4 b = ((const float4*)txtU)[o];
    float sa = a.x * a.x + a.y * a.y + a.z * a.z + a.w * a.w;
    float sb = b.x * b.x + b.y * b.y + b.z * b.z + b.w * b.w;
#pragma unroll
    for (int of = 8; of; of >>= 1) {
        sa += __shfl_xor_sync(0xffffffffu, sa, of);
        sb += __shfl_xor_sync(0xffffffffu, sb, of);
    }
    float ia = 0.55f / fmaxf(sqrtf(sa), 1e-12f);
    float ib = 0.55f / fmaxf(sqrtf(sb), 1e-12f);
    float4 r;
    r.x = (g.x + acc.x) * (1.0f / 3.0f) + a.x * ia + b.x * ib;
    r.y = (g.y + acc.y) * (1.0f / 3.0f) + a.y * ia + b.y * ib;
    r.z = (g.z + acc.z) * (1.0f / 3.0f) + a.z * ia + b.z * ib;
    r.w = (g.w + acc.w) * (1.0f / 3.0f) + a.w * ia + b.w * ib;
    ((float4*)u_out)[o] = r;
}

__global__ __launch_bounds__(256) void k_gnn_i2(const float* __restrict__ imgI,
                                                const float* __restrict__ txtI,
                                                float* __restrict__ i_out) {
    int warp = (blockIdx.x * 256 + threadIdx.x) >> 5;
    int lane = threadIdx.x & 31;
    int row = warp * 2 + (lane >> 4);
    if (row >= NI) return;
    int c = lane & 15;
    const uint2* __restrict__ X = (const uint2*)g_ue2_h;
    const int2* __restrict__ E = g_edge_i;
    int s = g_offs_i[row], e = g_offs_i[row + 1];
    float4 acc = make_float4(0.f, 0.f, 0.f, 0.f);
    for (int k = s; k < e; k += 8) {
        int2 ev[8];
#pragma unroll
        for (int u = 0; u < 8; u++) {
            int kk = k + u;
            int idx = (kk < e) ? kk : s;
            ev[u] = __ldg(&E[idx]);
            if (kk >= e) ev[u].y = 0;
        }
        uint2 raw[8];
#pragma unroll
        for (int u = 0; u < 8; u++) raw[u] = X[ev[u].x * 16 + c];
#pragma unroll
        for (int u = 0; u < 8; u++) fma_h2(acc, __int_as_float(ev[u].y), raw[u]);
    }
    int o = row * 16 + c;
    float4 g = ((const float4*)g_i_acc)[o];
    float4 a = ((const float4*)imgI)[o];
    float4 b = ((const float4*)txtI)[o];
    float sa = a.x * a.x + a.y * a.y + a.z * a.z + a.w * a.w;
    float sb = b.x * b.x + b.y * b.y + b.z * b.z + b.w * b.w;
#pragma unroll
    for (int of = 8; of; of >>= 1) {
        sa += __shfl_xor_sync(0xffffffffu, sa, of);
        sb += __shfl_xor_sync(0xffffffffu, sb, of);
    }
    float ia = 0.55f / fmaxf(sqrtf(sa), 1e-12f);
    float ib = 0.55f / fmaxf(sqrtf(sb), 1e-12f);
    float4 r;
    r.x = (g.x + acc.x) * (1.0f / 3.0f) + a.x * ia + b.x * ib;
    r.y = (g.y + acc.y) * (1.0f / 3.0f) + a.y * ia + b.y * ib;
    r.z = (g.z + acc.z) * (1.0f / 3.0f) + a.z * ia + b.z * ib;
    r.w = (g.w + acc.w) * (1.0f / 3.0f) + a.w * ia + b.w * ib;
    ((float4*)i_out)[o] = r;
}

// ----------------------------- launch ---------------------------------------
static cudaStream_t s_sB = 0, s_sC = 0, s_sD = 0;
static cudaEvent_t s_evFork = 0, s_evB = 0, s_evC = 0, s_evD = 0;

extern "C" void kernel_launch(void* const* d_in, const int* in_sizes, int n_in,
                              void* d_out, int out_size) {
    const float* image_feats = (const float*)d_in[0];
    const float* text_feats  = (const float*)d_in[1];
    const float* user_emb    = (const float*)d_in[2];
    const float* item_emb    = (const float*)d_in[3];
    const float* W_img       = (const float*)d_in[4];
    const float* b_img       = (const float*)d_in[5];
    const float* W_txt       = (const float*)d_in[6];
    const float* b_txt       = (const float*)d_in[7];
    const float* val_ui      = (const float*)d_in[8];
    const float* val_iu      = (const float*)d_in[9];
    const int*   edge_u      = (const int*)d_in[10];
    const int*   edge_i      = (const int*)d_in[11];

    float* out        = (float*)d_out;
    float* u_out      = out;
    float* i_out      = u_out + (size_t)NU * DD;
    float* image_item = i_out + (size_t)NI * DD;
    float* text_item  = image_item + (size_t)NI * DD;
    float* image_user = text_item + (size_t)NI * DD;
    float* text_user  = image_user + (size_t)NU * DD;

    if (s_sB == 0) {  // one-time resource creation (outside capture, 1st call)
        cudaStreamCreateWithFlags(&s_sB, cudaStreamNonBlocking);
        cudaStreamCreateWithFlags(&s_sC, cudaStreamNonBlocking);
        cudaStreamCreateWithFlags(&s_sD, cudaStreamNonBlocking);
        cudaEventCreateWithFlags(&s_evFork, cudaEventDisableTiming);
        cudaEventCreateWithFlags(&s_evB, cudaEventDisableTiming);
        cudaEventCreateWithFlags(&s_evC, cudaEventDisableTiming);
        cudaEventCreateWithFlags(&s_evD, cudaEventDisableTiming);
    }

    void* cnt_u_ptr = nullptr;
    void* cnt_i_ptr = nullptr;
    cudaGetSymbolAddress(&cnt_u_ptr, g_cnt_u);
    cudaGetSymbolAddress(&cnt_i_ptr, g_cnt_i);

    // fork three side streams off the capture stream
    cudaEventRecord(s_evFork, 0);
    cudaStreamWaitEvent(s_sB, s_evFork, 0);
    cudaStreamWaitEvent(s_sC, s_evFork, 0);
    cudaStreamWaitEvent(s_sD, s_evFork, 0);

    // branch B: tensor-core GEMMs (17KB smem blocks -> co-residency)
    k_linear_mma<1024, 0><<<(NI + 255) / 256, 512, 0, s_sB>>>(image_feats, W_img, b_img, NI);
    k_linear_mma<384, 1><<<(NI + 255) / 256, 512, 0, s_sB>>>(text_feats, W_txt, b_txt, NI);

    // branch C: stats chain
    k_stats<<<SPART, 256, 0, s_sC>>>(user_emb, item_emb);
    k_stats_fin<<<1, 128, 0, s_sC>>>();
    k_norm_items<<<512, 256, 0, s_sC>>>(item_emb);

    // branch D: item-side CSR
    cudaMemsetAsync(cnt_i_ptr, 0, NI * sizeof(int), s_sD);
    k_hist_i<<<512, 256, 0, s_sD>>>(edge_i);
    k_scan<1><<<1, 1024, 0, s_sD>>>();
    k_scatter_i<<<1024, 256, 0, s_sD>>>(edge_u, edge_i, val_iu);
    cudaEventRecord(s_evD, s_sD);

    // main branch: user-side CSR
    cudaMemsetAsync(cnt_u_ptr, 0, NU * sizeof(int));
    k_hist_u<<<512, 256>>>(edge_u);
    k_scan<0><<<1, 1024>>>();
    k_scatter_u<<<1024, 256>>>(edge_u, edge_i, val_ui);

    // join GEMM + stats before fused_u
    cudaEventRecord(s_evB, s_sB);
    cudaEventRecord(s_evC, s_sC);
    cudaStreamWaitEvent(0, s_evB, 0);
    cudaStreamWaitEvent(0, s_evC, 0);

    // fused modal + GNN layer-1 (user side)
    k_fused_u<<<(NU + 15) / 16, 256>>>(user_emb, image_user, text_user);

    // item side additionally needs the item CSR
    cudaStreamWaitEvent(0, s_evD, 0);
    k_fused_i<<<(NI + 15) / 16, 256>>>(item_emb, image_item, text_item);

    // GNN layer-2 fused with final combine
    k_gnn_u2<<<(NU + 15) / 16, 256>>>(image_user, text_user, u_out);
    k_gnn_i2<<<(NI + 15) / 16, 256>>>(image_item, text_item, i_out);
}